// round 2
// baseline (speedup 1.0000x reference)
#include <cuda_runtime.h>
#include <cuda_bf16.h>

// LIF scan, T=4, V_RESET=0, TAU=2, forward spike = heaviside(v_charged - 1).
// R2: 2x float4 per thread (8 front-batched LDG.128 -> MLP=8), streaming
// cache hints (__ldcs/__stcs) since both streams are touch-once.
// Memory-bound: ~620 MB total traffic.

#define T_STEPS 4

__device__ __forceinline__ void lif_step(float& v, float x, float& s) {
    // Match reference arithmetic exactly: v_charged = v + (x - v)/2
    float vc = fmaf(x - v, 0.5f, v);
    bool sp = (vc >= 1.0f);           // v_charged - V_THRESHOLD >= 0
    s = sp ? 1.0f : 0.0f;
    v = sp ? 0.0f : vc;               // hard reset to V_RESET=0
}

__device__ __forceinline__ void lif_lane4(const float4& a, const float4& b,
                                          const float4& c, const float4& d,
                                          float4& s0, float4& s1,
                                          float4& s2, float4& s3) {
    {
        float v = 0.0f;
        lif_step(v, a.x, s0.x); lif_step(v, b.x, s1.x);
        lif_step(v, c.x, s2.x); lif_step(v, d.x, s3.x);
    }
    {
        float v = 0.0f;
        lif_step(v, a.y, s0.y); lif_step(v, b.y, s1.y);
        lif_step(v, c.y, s2.y); lif_step(v, d.y, s3.y);
    }
    {
        float v = 0.0f;
        lif_step(v, a.z, s0.z); lif_step(v, b.z, s1.z);
        lif_step(v, c.z, s2.z); lif_step(v, d.z, s3.z);
    }
    {
        float v = 0.0f;
        lif_step(v, a.w, s0.w); lif_step(v, b.w, s1.w);
        lif_step(v, c.w, s2.w); lif_step(v, d.w, s3.w);
    }
}

__global__ void __launch_bounds__(256)
lif_kernel(const float4* __restrict__ x, float4* __restrict__ out, int n4) {
    // Each thread owns 2 adjacent float4 lanes (i0, i0+1) across all 4 timesteps.
    long long t = (long long)blockIdx.x * blockDim.x + threadIdx.x;
    long long i0 = 2 * t;
    if (i0 >= n4) return;

    const float4* p0 = x + i0;
    const float4* p1 = p0 + n4;
    const float4* p2 = p1 + n4;
    const float4* p3 = p2 + n4;

    // 8 front-batched streaming loads (independent of the v-chain).
    float4 a0 = __ldcs(p0),     a1 = __ldcs(p0 + 1);
    float4 b0 = __ldcs(p1),     b1 = __ldcs(p1 + 1);
    float4 c0 = __ldcs(p2),     c1 = __ldcs(p2 + 1);
    float4 d0 = __ldcs(p3),     d1 = __ldcs(p3 + 1);

    float4 s00, s01, s02, s03, s10, s11, s12, s13;
    lif_lane4(a0, b0, c0, d0, s00, s01, s02, s03);
    lif_lane4(a1, b1, c1, d1, s10, s11, s12, s13);

    float4* q0 = out + i0;
    float4* q1 = q0 + n4;
    float4* q2 = q1 + n4;
    float4* q3 = q2 + n4;

    __stcs(q0, s00); __stcs(q0 + 1, s10);
    __stcs(q1, s01); __stcs(q1 + 1, s11);
    __stcs(q2, s02); __stcs(q2 + 1, s12);
    __stcs(q3, s03); __stcs(q3 + 1, s13);
}

extern "C" void kernel_launch(void* const* d_in, const int* in_sizes, int n_in,
                              void* d_out, int out_size) {
    const float* x = (const float*)d_in[0];
    float* out = (float*)d_out;

    int total = in_sizes[0];             // T * N = 77,463,552
    int n = total / T_STEPS;             // 19,365,888 elements per timestep
    int n4 = n / 4;                      // 4,841,472 float4 lanes
    int n8 = n4 / 2;                     // 2,420,736 threads (n4 is even)

    int threads = 256;
    int blocks = (n8 + threads - 1) / threads;
    lif_kernel<<<blocks, threads>>>((const float4*)x, (float4*)out, n4);
}

// round 3
// speedup vs baseline: 1.0314x; 1.0314x over previous
#include <cuda_runtime.h>
#include <cuda_bf16.h>

// LIF scan, T=4, V_RESET=0, TAU=2, forward spike = heaviside(v_charged - 1).
// R3: R1 structure (1 float4/thread, 4 front-batched LDG.128, occ ~78%)
// + single change: streaming cache hints (__ldcs/__stcs), both streams
// are touch-once. Memory-bound: ~620 MB total traffic.

#define T_STEPS 4

__device__ __forceinline__ void lif_step(float& v, float x, float& s) {
    // Match reference arithmetic exactly: v_charged = v + (x - v)/2
    float vc = fmaf(x - v, 0.5f, v);
    bool sp = (vc >= 1.0f);           // v_charged - V_THRESHOLD >= 0
    s = sp ? 1.0f : 0.0f;
    v = sp ? 0.0f : vc;               // hard reset to V_RESET=0
}

__global__ void __launch_bounds__(256)
lif_kernel(const float4* __restrict__ x, float4* __restrict__ out, int n4) {
    int i = blockIdx.x * blockDim.x + threadIdx.x;
    if (i >= n4) return;

    // Front-batched streaming loads: independent of the v-chain (MLP=4).
    float4 x0 = __ldcs(x + i);
    float4 x1 = __ldcs(x + i + (size_t)n4);
    float4 x2 = __ldcs(x + i + (size_t)2 * n4);
    float4 x3 = __ldcs(x + i + (size_t)3 * n4);

    float4 s0, s1, s2, s3;

    // 4 independent lanes, each a 4-step sequential scan.
    {
        float v = 0.0f;
        lif_step(v, x0.x, s0.x); lif_step(v, x1.x, s1.x);
        lif_step(v, x2.x, s2.x); lif_step(v, x3.x, s3.x);
    }
    {
        float v = 0.0f;
        lif_step(v, x0.y, s0.y); lif_step(v, x1.y, s1.y);
        lif_step(v, x2.y, s2.y); lif_step(v, x3.y, s3.y);
    }
    {
        float v = 0.0f;
        lif_step(v, x0.z, s0.z); lif_step(v, x1.z, s1.z);
        lif_step(v, x2.z, s2.z); lif_step(v, x3.z, s3.z);
    }
    {
        float v = 0.0f;
        lif_step(v, x0.w, s0.w); lif_step(v, x1.w, s1.w);
        lif_step(v, x2.w, s2.w); lif_step(v, x3.w, s3.w);
    }

    __stcs(out + i,                  s0);
    __stcs(out + i + (size_t)n4,     s1);
    __stcs(out + i + (size_t)2 * n4, s2);
    __stcs(out + i + (size_t)3 * n4, s3);
}

extern "C" void kernel_launch(void* const* d_in, const int* in_sizes, int n_in,
                              void* d_out, int out_size) {
    const float* x = (const float*)d_in[0];
    float* out = (float*)d_out;

    int total = in_sizes[0];             // T * N = 77,463,552
    int n = total / T_STEPS;             // 19,365,888 elements per timestep
    int n4 = n / 4;                      // 4,841,472 float4 lanes (768 % 4 == 0)

    int threads = 256;
    int blocks = (n4 + threads - 1) / threads;
    lif_kernel<<<blocks, threads>>>((const float4*)x, (float4*)out, n4);
}